// round 1
// baseline (speedup 1.0000x reference)
#include <cuda_runtime.h>
#include <math.h>

// ---------------------------------------------------------------------------
// LogNCDE: depth-2 log-ODE scan.
//   s1,s2 signatures computed in-kernel; per-step:
//     fwd MLP  : z0=sp(Wv0 h+b), z1=sp(Wv1 z0+b), V=tanh(Wv2 z1+b)  (D=8,S=64)
//     bracket  : w_d = sum_e C[d,e] V[e,:]  (C antisym from Lyndon coeffs)
//                q=Wv0 w_d; p=sig0*q; u'=Wv1 p; u=sig1*u'; r_d=(1-V_d^2)*(Wv2_d u_d)
//     update   : h += a.V + sum_d r_d ;  readout out = Wr h + br
// ---------------------------------------------------------------------------

namespace {
constexpr int kB   = 32;
constexpr int kT   = 2049;
constexpr int kD   = 8;
constexpr int kS   = 64;
constexpr int kH   = 128;
constexpr int kP   = 28;
constexpr int kNW  = 128;
constexpr int kWin = 16;
constexpr int kOut = 8;
constexpr int NT   = 512;   // threads per CTA
constexpr int KC   = 32;    // Wv2T k-rows cached in smem
constexpr int kY   = kD * kS;   // 512 rows of Wv2

// shared-memory layout (float offsets)
constexpr int OFF_WV0T = 0;                       // [k<64][o<128]
constexpr int OFF_WV1T = OFF_WV0T + kS * kH;      // [k<128][o<128]
constexpr int OFF_WV2C = OFF_WV1T + kH * kH;      // [k<KC][o<512]
constexpr int OFF_SIGS = OFF_WV2C + KC * 512;     // [n<128][36]
constexpr int OFF_BV0  = OFF_SIGS + kNW * 36;
constexpr int OFF_BV1  = OFF_BV0 + kH;
constexpr int OFF_BV2  = OFF_BV1 + kH;
constexpr int OFF_WR   = OFF_BV2 + kY;            // [o<8][a<64]
constexpr int OFF_BR   = OFF_WR + kOut * kS;
constexpr int OFF_H    = OFF_BR + 8;
constexpr int OFF_Z0   = OFF_H + kS;
constexpr int OFF_D0   = OFF_Z0 + kH;
constexpr int OFF_Z1   = OFF_D0 + kH;
constexpr int OFF_D1   = OFF_Z1 + kH;
constexpr int OFF_V    = OFF_D1 + kH;             // 512
constexpr int OFF_TD   = OFF_V + kY;              // 512 : 1 - V^2
constexpr int OFF_C    = OFF_TD + kY;             // 64  : antisym coeff matrix
constexpr int OFF_WT   = OFF_C + 64;              // [d<8][k<64]
constexpr int OFF_PT   = OFF_WT + kD * kS;        // [d<8][k<128]
constexpr int OFF_UT   = OFF_PT + kD * kH;        // [d<8][k<128]
constexpr int OFF_R    = OFF_UT + kD * kH;        // 512
constexpr int OFF_PART = OFF_R + kY;              // 2048 scratch partials
constexpr int SMEMF    = OFF_PART + 2048;         // ~53.6K floats = ~210 KB
}  // namespace

__device__ float g_Wv2T[kH * kY];   // transposed Wv2: [k][o], o = d*kS + a

static __device__ const int c_II[kP] =
    {0,0,0,0,0,0,0,1,1,1,1,1,1,2,2,2,2,2,3,3,3,3,4,4,4,5,5,6};
static __device__ const int c_JJ[kP] =
    {1,2,3,4,5,6,7,2,3,4,5,6,7,3,4,5,6,7,4,5,6,7,5,6,7,6,7,7};

__global__ void prep_transpose_kernel(const float* __restrict__ Wv2) {
    int i = blockIdx.x * blockDim.x + threadIdx.x;
    if (i < kH * kY) {
        int k = i >> 9;        // /512
        int o = i & 511;
        g_Wv2T[i] = Wv2[o * kH + k];
    }
}

__device__ __forceinline__ float sp_f(float x) {      // softplus
    return (x > 20.f) ? x : log1pf(expf(x));
}
__device__ __forceinline__ float sg_f(float x) {      // sigmoid
    return 1.f / (1.f + expf(-x));
}

__global__ __launch_bounds__(NT, 1)
void logncde_scan_kernel(
    const float* __restrict__ x,
    const float* __restrict__ Wi0, const float* __restrict__ bi0,
    const float* __restrict__ Wi1, const float* __restrict__ bi1,
    const float* __restrict__ Wi2, const float* __restrict__ bi2,
    const float* __restrict__ Wv0, const float* __restrict__ bv0,
    const float* __restrict__ Wv1, const float* __restrict__ bv1,
    const float* __restrict__ bv2,
    const float* __restrict__ Wr,  const float* __restrict__ br,
    float* __restrict__ out)
{
    extern __shared__ float sm[];
    const int t = threadIdx.x;
    const int b = blockIdx.x;

    // ---- one-time: stage weights (transposed: lane-consecutive outputs) ----
    for (int i = t; i < kS * kH; i += NT) {
        int k = i >> 7, o = i & 127;
        sm[OFF_WV0T + i] = Wv0[o * kS + k];
    }
    for (int i = t; i < kH * kH; i += NT) {
        int k = i >> 7, o = i & 127;
        sm[OFF_WV1T + i] = Wv1[o * kH + k];
    }
    for (int i = t; i < KC * 512; i += NT) sm[OFF_WV2C + i] = g_Wv2T[i];
    for (int i = t; i < kH; i += NT) { sm[OFF_BV0 + i] = bv0[i]; sm[OFF_BV1 + i] = bv1[i]; }
    for (int i = t; i < kY; i += NT) sm[OFF_BV2 + i] = bv2[i];
    for (int i = t; i < kOut * kS; i += NT) sm[OFF_WR + i] = Wr[i];
    if (t < kOut) sm[OFF_BR + t] = br[t];

    // ---- one-time: depth-2 log-signatures, one window per thread ----
    if (t < kNW) {
        const float* xb = x + (size_t)b * kT * kD + (size_t)t * kWin * kD;
        float cum[kD], prev[kD], Mm[kD * kD];
        #pragma unroll
        for (int i = 0; i < kD; i++) { cum[i] = 0.f; prev[i] = xb[i]; }
        #pragma unroll
        for (int i = 0; i < kD * kD; i++) Mm[i] = 0.f;
        for (int w = 0; w < kWin; w++) {
            float dl[kD];
            #pragma unroll
            for (int j = 0; j < kD; j++) {
                float c = xb[(w + 1) * kD + j];
                dl[j] = c - prev[j];
                prev[j] = c;
            }
            #pragma unroll
            for (int i = 0; i < kD; i++)
                #pragma unroll
                for (int j = 0; j < kD; j++)
                    Mm[i * kD + j] = fmaf(cum[i], dl[j], Mm[i * kD + j]);
            #pragma unroll
            for (int i = 0; i < kD; i++) cum[i] += dl[i];
        }
        float* sgw = &sm[OFF_SIGS + t * 36];
        #pragma unroll
        for (int i = 0; i < kD; i++) sgw[i] = cum[i];
        #pragma unroll
        for (int p = 0; p < kP; p++) {
            int i = c_II[p], j = c_JJ[p];
            sgw[8 + p] = 0.5f * (Mm[i * kD + j] - Mm[j * kD + i]);
        }
    }
    __syncthreads();

    // ---- one-time: initial MLP h0 (reuse z0/z1 scratch) ----
    {
        const float* x0 = x + (size_t)b * kT * kD;
        if (t < kH) {
            float acc = bi0[t];
            #pragma unroll
            for (int k = 0; k < kD; k++) acc = fmaf(Wi0[t * kD + k], x0[k], acc);
            sm[OFF_Z0 + t] = sp_f(acc);
        }
        __syncthreads();
        if (t < kH) {
            float acc = bi1[t];
            #pragma unroll 16
            for (int k = 0; k < kH; k++) acc = fmaf(Wi1[t * kH + k], sm[OFF_Z0 + k], acc);
            sm[OFF_Z1 + t] = sp_f(acc);
        }
        __syncthreads();
        if (t < kS) {
            float acc = bi2[t];
            #pragma unroll 16
            for (int k = 0; k < kH; k++) acc = fmaf(Wi2[t * kH + k], sm[OFF_Z1 + k], acc);
            sm[OFF_H + t] = acc;
        }
        __syncthreads();
    }

    const float4* gw = (const float4*)g_Wv2T;
    const float4* wc = (const float4*)&sm[OFF_WV2C];
    float4* part4 = (float4*)&sm[OFF_PART];

    // ============================ scan loop ============================
    for (int n = 0; n < kNW; n++) {
        const float* sgn = &sm[OFF_SIGS + n * 36];

        // --- P1: z0 = sp(Wv0 h + b); readout of h_n; build C from b-coeffs
        if (t < kH) {
            float acc = sm[OFF_BV0 + t];
            #pragma unroll
            for (int k = 0; k < kS; k++)
                acc = fmaf(sm[OFF_WV0T + k * kH + t], sm[OFF_H + k], acc);
            sm[OFF_Z0 + t] = sp_f(acc);
            sm[OFF_D0 + t] = sg_f(acc);
        } else if (t < kH + kOut) {
            int o = t - kH;
            float acc = sm[OFF_BR + o];
            #pragma unroll
            for (int a = 0; a < kS; a++)
                acc = fmaf(sm[OFF_WR + o * kS + a], sm[OFF_H + a], acc);
            out[((size_t)b * (kNW + 1) + n) * kOut + o] = acc;
        } else if (t < kH + kOut + kP) {
            int p = t - kH - kOut;
            int i = c_II[p], j = c_JJ[p];
            float bc = sgn[8 + p];
            sm[OFF_C + j * kD + i] = bc;
            sm[OFF_C + i * kD + j] = -bc;
        } else if (t < kH + kOut + kP + kD) {
            int dg = t - kH - kOut - kP;
            sm[OFF_C + dg * kD + dg] = 0.f;
        }
        __syncthreads();

        // --- P2: z1 = sp(Wv1 z0 + b), 4-way K split
        {
            int o = t & 127, q = t >> 7;
            int k0 = q * 32;
            float acc = 0.f;
            #pragma unroll
            for (int kk = 0; kk < 32; kk++)
                acc = fmaf(sm[OFF_WV1T + (k0 + kk) * kH + o], sm[OFF_Z0 + k0 + kk], acc);
            sm[OFF_PART + q * kH + o] = acc;
        }
        __syncthreads();
        if (t < kH) {
            float s = sm[OFF_PART + t] + sm[OFF_PART + kH + t] +
                      sm[OFF_PART + 2 * kH + t] + sm[OFF_PART + 3 * kH + t] +
                      sm[OFF_BV1 + t];
            sm[OFF_Z1 + t] = sp_f(s);
            sm[OFF_D1 + t] = sg_f(s);
        }
        __syncthreads();

        // --- P3: V = tanh(Wv2 z1 + b), 512 outs, float4 over outs, 4-way K split
        {
            int og = t & 127, q = t >> 7;
            float4 acc = make_float4(0.f, 0.f, 0.f, 0.f);
            if (q == 0) {
                #pragma unroll
                for (int k = 0; k < 32; k++) {
                    float4 w = wc[k * 128 + og];
                    float zz = sm[OFF_Z1 + k];
                    acc.x = fmaf(w.x, zz, acc.x); acc.y = fmaf(w.y, zz, acc.y);
                    acc.z = fmaf(w.z, zz, acc.z); acc.w = fmaf(w.w, zz, acc.w);
                }
            } else {
                int k0 = q * 32;
                #pragma unroll
                for (int kk = 0; kk < 32; kk++) {
                    float4 w = __ldg(&gw[(k0 + kk) * 128 + og]);
                    float zz = sm[OFF_Z1 + k0 + kk];
                    acc.x = fmaf(w.x, zz, acc.x); acc.y = fmaf(w.y, zz, acc.y);
                    acc.z = fmaf(w.z, zz, acc.z); acc.w = fmaf(w.w, zz, acc.w);
                }
            }
            part4[q * 128 + og] = acc;
        }
        __syncthreads();
        {
            float s = sm[OFF_PART + t] + sm[OFF_PART + 512 + t] +
                      sm[OFF_PART + 1024 + t] + sm[OFF_PART + 1536 + t] +
                      sm[OFF_BV2 + t];
            float y = tanhf(s);
            sm[OFF_V + t] = y;
            sm[OFF_TD + t] = 1.f - y * y;
        }
        __syncthreads();

        // --- P4: tangents w_d = sum_e C[d,e] V[e,:]
        {
            int dI = t >> 6, bb = t & 63;
            float acc = 0.f;
            #pragma unroll
            for (int e = 0; e < kD; e++)
                acc = fmaf(sm[OFF_C + dI * kD + e], sm[OFF_V + e * kS + bb], acc);
            sm[OFF_WT + dI * kS + bb] = acc;
        }
        __syncthreads();

        // --- P5: p_d = sig0 * (Wv0 w_d), two d per thread
        {
            int o = t & 127, g = t >> 7;
            int da = 2 * g, db = 2 * g + 1;
            float a0 = 0.f, a1 = 0.f;
            #pragma unroll
            for (int k = 0; k < kS; k++) {
                float w = sm[OFF_WV0T + k * kH + o];
                a0 = fmaf(w, sm[OFF_WT + da * kS + k], a0);
                a1 = fmaf(w, sm[OFF_WT + db * kS + k], a1);
            }
            float dd = sm[OFF_D0 + o];
            sm[OFF_PT + da * kH + o] = a0 * dd;
            sm[OFF_PT + db * kH + o] = a1 * dd;
        }
        __syncthreads();

        // --- P6: u_d = sig1 * (Wv1 p_d), two d per thread
        {
            int o = t & 127, g = t >> 7;
            int da = 2 * g, db = 2 * g + 1;
            float a0 = 0.f, a1 = 0.f;
            #pragma unroll 16
            for (int k = 0; k < kH; k++) {
                float w = sm[OFF_WV1T + k * kH + o];
                a0 = fmaf(w, sm[OFF_PT + da * kH + k], a0);
                a1 = fmaf(w, sm[OFF_PT + db * kH + k], a1);
            }
            float dd = sm[OFF_D1 + o];
            sm[OFF_UT + da * kH + o] = a0 * dd;
            sm[OFF_UT + db * kH + o] = a1 * dd;
        }
        __syncthreads();

        // --- P7: r[(d,a)] = (1-V^2) * (Wv2_block_d[a,:] . u_d)
        {
            int og = t & 127, q = t >> 7;
            int dI = og >> 4;                   // 4*og / 64
            float4 acc = make_float4(0.f, 0.f, 0.f, 0.f);
            if (q == 0) {
                #pragma unroll
                for (int k = 0; k < 32; k++) {
                    float4 w = wc[k * 128 + og];
                    float uu = sm[OFF_UT + dI * kH + k];
                    acc.x = fmaf(w.x, uu, acc.x); acc.y = fmaf(w.y, uu, acc.y);
                    acc.z = fmaf(w.z, uu, acc.z); acc.w = fmaf(w.w, uu, acc.w);
                }
            } else {
                int k0 = q * 32;
                #pragma unroll
                for (int kk = 0; kk < 32; kk++) {
                    float4 w = __ldg(&gw[(k0 + kk) * 128 + og]);
                    float uu = sm[OFF_UT + dI * kH + k0 + kk];
                    acc.x = fmaf(w.x, uu, acc.x); acc.y = fmaf(w.y, uu, acc.y);
                    acc.z = fmaf(w.z, uu, acc.z); acc.w = fmaf(w.w, uu, acc.w);
                }
            }
            part4[q * 128 + og] = acc;
        }
        __syncthreads();
        {
            float s = sm[OFF_PART + t] + sm[OFF_PART + 512 + t] +
                      sm[OFF_PART + 1024 + t] + sm[OFF_PART + 1536 + t];
            sm[OFF_R + t] = s * sm[OFF_TD + t];
        }
        __syncthreads();

        // --- P8: h += a.V + sum_d r_d
        if (t < kS) {
            float acc = sm[OFF_H + t];
            #pragma unroll
            for (int d = 0; d < kD; d++) {
                acc = fmaf(sgn[d], sm[OFF_V + d * kS + t], acc);
                acc += sm[OFF_R + d * kS + t];
            }
            sm[OFF_H + t] = acc;
        }
        __syncthreads();
    }

    // final readout (n = NWIN)
    if (t < kOut) {
        float acc = sm[OFF_BR + t];
        #pragma unroll
        for (int a = 0; a < kS; a++)
            acc = fmaf(sm[OFF_WR + t * kS + a], sm[OFF_H + a], acc);
        out[((size_t)b * (kNW + 1) + kNW) * kOut + t] = acc;
    }
}

extern "C" void kernel_launch(void* const* d_in, const int* in_sizes, int n_in,
                              void* d_out, int out_size) {
    // metadata order: ts, x, Wi0,bi0, Wi1,bi1, Wi2,bi2, Wv0,bv0, Wv1,bv1, Wv2,bv2, Wr,br
    const float* x   = (const float*)d_in[1];
    const float* Wi0 = (const float*)d_in[2];
    const float* bi0 = (const float*)d_in[3];
    const float* Wi1 = (const float*)d_in[4];
    const float* bi1 = (const float*)d_in[5];
    const float* Wi2 = (const float*)d_in[6];
    const float* bi2 = (const float*)d_in[7];
    const float* Wv0 = (const float*)d_in[8];
    const float* bv0 = (const float*)d_in[9];
    const float* Wv1 = (const float*)d_in[10];
    const float* bv1 = (const float*)d_in[11];
    const float* Wv2 = (const float*)d_in[12];
    const float* bv2 = (const float*)d_in[13];
    const float* Wr  = (const float*)d_in[14];
    const float* br  = (const float*)d_in[15];
    float* out = (float*)d_out;

    prep_transpose_kernel<<<(kH * kY + 511) / 512, 512>>>(Wv2);

    cudaFuncSetAttribute(logncde_scan_kernel,
                         cudaFuncAttributeMaxDynamicSharedMemorySize,
                         SMEMF * (int)sizeof(float));
    logncde_scan_kernel<<<kB, NT, SMEMF * sizeof(float)>>>(
        x, Wi0, bi0, Wi1, bi1, Wi2, bi2,
        Wv0, bv0, Wv1, bv1, bv2, Wr, br, out);
}

// round 2
// speedup vs baseline: 1.8339x; 1.8339x over previous
#include <cuda_runtime.h>
#include <cooperative_groups.h>
#include <math.h>

namespace cg = cooperative_groups;

// ---------------------------------------------------------------------------
// LogNCDE depth-2 log-ODE scan, 4-CTA cluster per batch element.
// Rank r owns channels d∈{2r,2r+1} and Wv2 rows [128r,128r+128) (smem-resident).
// Per step: replicated z0,z1 -> V slice (gather) -> 2 tangent JVPs -> bracket
// partial (all-reduce) -> h update (replicated).
// ---------------------------------------------------------------------------

namespace {
constexpr int kB   = 32;
constexpr int kT   = 2049;
constexpr int kD   = 8;
constexpr int kS   = 64;
constexpr int kH   = 128;
constexpr int kP   = 28;
constexpr int kNW  = 128;
constexpr int kWin = 16;
constexpr int kOut = 8;
constexpr int CL   = 4;     // cluster size
constexpr int NT   = 256;   // threads per CTA

// shared-memory layout (float offsets)
constexpr int OFF_WV0T  = 0;                        // [k<64][o<128]
constexpr int OFF_WV1T  = OFF_WV0T + kS * kH;       // [k<128][o<128]
constexpr int OFF_WV2TS = OFF_WV1T + kH * kH;       // [k<128][og<128] slice
constexpr int OFF_SIGS  = OFF_WV2TS + kH * kH;      // [n<128][36]
constexpr int OFF_BV0   = OFF_SIGS + kNW * 36;
constexpr int OFF_BV1   = OFF_BV0 + kH;
constexpr int OFF_BV2S  = OFF_BV1 + kH;             // slice (128)
constexpr int OFF_WR    = OFF_BV2S + kH;            // [o<8][a<64]
constexpr int OFF_BR    = OFF_WR + kOut * kS;
constexpr int OFF_H     = OFF_BR + 8;               // 64
constexpr int OFF_Z0    = OFF_H + kS;               // 128
constexpr int OFF_D0    = OFF_Z0 + kH;
constexpr int OFF_Z1    = OFF_D0 + kH;
constexpr int OFF_D1    = OFF_Z1 + kH;
constexpr int OFF_V     = OFF_D1 + kH;              // 2 x 512 (double buffered)
constexpr int OFF_TDS   = OFF_V + 2 * 512;          // 128 own slice: 1 - V^2
constexpr int OFF_C     = OFF_TDS + kH;             // 2 x 8
constexpr int OFF_WT    = OFF_C + 16;               // 2 x 64 tangents
constexpr int OFF_PT    = OFF_WT + 2 * kS;          // 2 x 128
constexpr int OFF_UT    = OFF_PT + 2 * kH;          // 2 x 128
constexpr int OFF_RD    = OFF_UT + 2 * kH;          // 128
constexpr int OFF_RSLOT = OFF_RD + kH;              // 4 x 64
constexpr int OFF_PART  = OFF_RSLOT + CL * kS;      // 256 reduce scratch
constexpr int SMEMF     = OFF_PART + 256;           // ~49.5K floats ≈ 198 KB
}  // namespace

static __device__ const int c_II[kP] =
    {0,0,0,0,0,0,0,1,1,1,1,1,1,2,2,2,2,2,3,3,3,3,4,4,4,5,5,6};
static __device__ const int c_JJ[kP] =
    {1,2,3,4,5,6,7,2,3,4,5,6,7,3,4,5,6,7,4,5,6,7,5,6,7,6,7,7};

__device__ __forceinline__ float sp_f(float x) {      // softplus
    return (x > 20.f) ? x : log1pf(expf(x));
}
__device__ __forceinline__ float sg_f(float x) {      // sigmoid
    return 1.f / (1.f + expf(-x));
}
__device__ __forceinline__ int pidx(int i, int j) {   // Lyndon pair index, i<j
    return 7 * i - (i * (i - 1)) / 2 + (j - i - 1);
}

__global__ __launch_bounds__(NT, 1) __cluster_dims__(CL, 1, 1)
void logncde_cluster_kernel(
    const float* __restrict__ x,
    const float* __restrict__ Wi0, const float* __restrict__ bi0,
    const float* __restrict__ Wi1, const float* __restrict__ bi1,
    const float* __restrict__ Wi2, const float* __restrict__ bi2,
    const float* __restrict__ Wv0, const float* __restrict__ bv0,
    const float* __restrict__ Wv1, const float* __restrict__ bv1,
    const float* __restrict__ Wv2, const float* __restrict__ bv2,
    const float* __restrict__ Wr,  const float* __restrict__ br,
    float* __restrict__ out)
{
    extern __shared__ float sm[];
    cg::cluster_group cluster = cg::this_cluster();
    const int t    = threadIdx.x;
    const int rank = (int)cluster.block_rank();
    const int b    = blockIdx.x >> 2;          // cluster id == batch
    const int d0g  = 2 * rank;                 // first owned channel

    // peer smem base pointers (the 3 other ranks)
    float* peer[CL - 1];
    #pragma unroll
    for (int p = 1; p < CL; p++)
        peer[p - 1] = cluster.map_shared_rank(sm, (rank + p) & (CL - 1));

    // ---- one-time: stage weights (transposed: lane-consecutive outputs) ----
    for (int i = t; i < kS * kH; i += NT) {
        int k = i >> 7, o = i & 127;
        sm[OFF_WV0T + i] = Wv0[o * kS + k];
    }
    for (int i = t; i < kH * kH; i += NT) {
        int k = i >> 7, o = i & 127;
        sm[OFF_WV1T + i] = Wv1[o * kH + k];
    }
    for (int i = t; i < kH * kH; i += NT) {
        int k = i >> 7, og = i & 127;
        sm[OFF_WV2TS + i] = Wv2[(size_t)(kH * rank + og) * kH + k];
    }
    for (int i = t; i < kH; i += NT) {
        sm[OFF_BV0 + i]  = bv0[i];
        sm[OFF_BV1 + i]  = bv1[i];
        sm[OFF_BV2S + i] = bv2[kH * rank + i];
    }
    for (int i = t; i < kOut * kS; i += NT) sm[OFF_WR + i] = Wr[i];
    if (t < kOut) sm[OFF_BR + t] = br[t];

    // ---- one-time: depth-2 log-signatures (one window per thread, t<128) ----
    if (t < kNW) {
        const float* xb = x + (size_t)b * kT * kD + (size_t)t * kWin * kD;
        float cum[kD], prev[kD], Mm[kD * kD];
        #pragma unroll
        for (int i = 0; i < kD; i++) { cum[i] = 0.f; prev[i] = xb[i]; }
        #pragma unroll
        for (int i = 0; i < kD * kD; i++) Mm[i] = 0.f;
        for (int w = 0; w < kWin; w++) {
            float dl[kD];
            #pragma unroll
            for (int j = 0; j < kD; j++) {
                float c = xb[(w + 1) * kD + j];
                dl[j] = c - prev[j];
                prev[j] = c;
            }
            #pragma unroll
            for (int i = 0; i < kD; i++)
                #pragma unroll
                for (int j = 0; j < kD; j++)
                    Mm[i * kD + j] = fmaf(cum[i], dl[j], Mm[i * kD + j]);
            #pragma unroll
            for (int i = 0; i < kD; i++) cum[i] += dl[i];
        }
        float* sgw = &sm[OFF_SIGS + t * 36];
        #pragma unroll
        for (int i = 0; i < kD; i++) sgw[i] = cum[i];
        #pragma unroll
        for (int p = 0; p < kP; p++) {
            int i = c_II[p], j = c_JJ[p];
            sgw[8 + p] = 0.5f * (Mm[i * kD + j] - Mm[j * kD + i]);
        }
    }
    __syncthreads();

    // ---- one-time: initial MLP h0 (replicated; identical across ranks) ----
    {
        const float* x0 = x + (size_t)b * kT * kD;
        if (t < kH) {
            float acc = bi0[t];
            #pragma unroll
            for (int k = 0; k < kD; k++) acc = fmaf(Wi0[t * kD + k], x0[k], acc);
            sm[OFF_Z0 + t] = sp_f(acc);
        }
        __syncthreads();
        if (t < kH) {
            float acc = bi1[t];
            #pragma unroll 16
            for (int k = 0; k < kH; k++) acc = fmaf(Wi1[t * kH + k], sm[OFF_Z0 + k], acc);
            sm[OFF_Z1 + t] = sp_f(acc);
        }
        __syncthreads();
        if (t < kS) {
            float acc = bi2[t];
            #pragma unroll 16
            for (int k = 0; k < kH; k++) acc = fmaf(Wi2[t * kH + k], sm[OFF_Z1 + k], acc);
            sm[OFF_H + t] = acc;
        }
        __syncthreads();
    }

    cluster.sync();   // everyone staged before cross-CTA traffic begins

    // ============================ scan loop ============================
    for (int n = 0; n < kNW; n++) {
        const float* sgn = &sm[OFF_SIGS + n * 36];
        const int parV = (n & 1) * 512;

        // --- A: z0 = sp(Wv0 h + b) (t<128); rank0 readout; C build
        if (t < kH) {
            float acc = sm[OFF_BV0 + t];
            #pragma unroll
            for (int k = 0; k < kS; k++)
                acc = fmaf(sm[OFF_WV0T + k * kH + t], sm[OFF_H + k], acc);
            sm[OFF_Z0 + t] = sp_f(acc);
            sm[OFF_D0 + t] = sg_f(acc);
        } else if (t < kH + kOut) {
            if (rank == 0) {
                int o = t - kH;
                float acc = sm[OFF_BR + o];
                #pragma unroll
                for (int a = 0; a < kS; a++)
                    acc = fmaf(sm[OFF_WR + o * kS + a], sm[OFF_H + a], acc);
                out[((size_t)b * (kNW + 1) + n) * kOut + o] = acc;
            }
        } else if (t < kH + kOut + 16) {
            // C[dl][e] for own channels: w_d = sum_e C[d,e] V_e
            int idx = t - kH - kOut;
            int dl = idx >> 3, e = idx & 7;
            int d = d0g + dl;
            float v = 0.f;
            if (e < d)      v =  sgn[8 + pidx(e, d)];
            else if (e > d) v = -sgn[8 + pidx(d, e)];
            sm[OFF_C + dl * 8 + e] = v;
        }
        __syncthreads();

        // --- B: z1 = sp(Wv1 z0 + b), 2-way K split over 256 threads
        {
            int o = t & 127, q = t >> 7;
            int k0 = q * 64;
            float acc = 0.f;
            #pragma unroll
            for (int kk = 0; kk < 64; kk++)
                acc = fmaf(sm[OFF_WV1T + (k0 + kk) * kH + o], sm[OFF_Z0 + k0 + kk], acc);
            sm[OFF_PART + q * kH + o] = acc;
        }
        __syncthreads();
        if (t < kH) {
            float s = sm[OFF_PART + t] + sm[OFF_PART + kH + t] + sm[OFF_BV1 + t];
            sm[OFF_Z1 + t] = sp_f(s);
            sm[OFF_D1 + t] = sg_f(s);
        }
        __syncthreads();

        // --- C: V slice = tanh(Wv2_slice z1 + b), then broadcast to peers
        {
            int og = t & 127, q = t >> 7;
            int k0 = q * 64;
            float acc = 0.f;
            #pragma unroll
            for (int kk = 0; kk < 64; kk++)
                acc = fmaf(sm[OFF_WV2TS + (k0 + kk) * kH + og], sm[OFF_Z1 + k0 + kk], acc);
            sm[OFF_PART + q * kH + og] = acc;
        }
        __syncthreads();
        if (t < kH) {
            float s = sm[OFF_PART + t] + sm[OFF_PART + kH + t] + sm[OFF_BV2S + t];
            float v = tanhf(s);
            int vi = OFF_V + parV + kH * rank + t;
            sm[vi] = v;
            sm[OFF_TDS + t] = 1.f - v * v;
            peer[0][vi] = v;
            peer[1][vi] = v;
            peer[2][vi] = v;
        }
        cluster.sync();   // V(n) fully gathered everywhere

        // --- D: tangents w_d = sum_e C[d,e] V_e for own 2 channels
        if (t < kH) {
            int dl = t >> 6, a = t & 63;
            float acc = 0.f;
            #pragma unroll
            for (int e = 0; e < kD; e++)
                acc = fmaf(sm[OFF_C + dl * 8 + e], sm[OFF_V + parV + e * kS + a], acc);
            sm[OFF_WT + dl * kS + a] = acc;
        }
        __syncthreads();

        // --- E: p_d = D0 .* (Wv0 w_d), 2 channels x 128 outs = 256 threads
        {
            int dl = t >> 7, o = t & 127;
            float acc = 0.f;
            #pragma unroll
            for (int k = 0; k < kS; k++)
                acc = fmaf(sm[OFF_WV0T + k * kH + o], sm[OFF_WT + dl * kS + k], acc);
            sm[OFF_PT + dl * kH + o] = acc * sm[OFF_D0 + o];
        }
        __syncthreads();

        // --- F: u_d = D1 .* (Wv1 p_d), 2 channels x 128 outs
        {
            int dl = t >> 7, o = t & 127;
            float acc = 0.f;
            #pragma unroll 16
            for (int k = 0; k < kH; k++)
                acc = fmaf(sm[OFF_WV1T + k * kH + o], sm[OFF_PT + dl * kH + k], acc);
            sm[OFF_UT + dl * kH + o] = acc * sm[OFF_D1 + o];
        }
        __syncthreads();

        // --- G: r_d = TD .* (Wv2_d u_d); bracket partial; all-reduce
        {
            int slot = t & 127, q = t >> 7;     // slot = dl*64 + a = local og
            int dl = slot >> 6;
            int k0 = q * 64;
            float acc = 0.f;
            #pragma unroll
            for (int kk = 0; kk < 64; kk++)
                acc = fmaf(sm[OFF_WV2TS + (k0 + kk) * kH + slot],
                           sm[OFF_UT + dl * kH + k0 + kk], acc);
            sm[OFF_PART + q * kH + slot] = acc;
        }
        __syncthreads();
        if (t < kH) {
            sm[OFF_RD + t] = (sm[OFF_PART + t] + sm[OFF_PART + kH + t]) * sm[OFF_TDS + t];
        }
        __syncthreads();
        if (t < kS) {
            float rs = sm[OFF_RD + t] + sm[OFF_RD + kS + t];
            int ri = OFF_RSLOT + kS * rank + t;
            sm[ri] = rs;
            peer[0][ri] = rs;
            peer[1][ri] = rs;
            peer[2][ri] = rs;
        }
        cluster.sync();   // bracket partials gathered everywhere

        // --- H: h += a.V + sum_r rslot (replicated, identical across ranks)
        if (t < kS) {
            float acc = sm[OFF_H + t];
            #pragma unroll
            for (int d = 0; d < kD; d++)
                acc = fmaf(sgn[d], sm[OFF_V + parV + d * kS + t], acc);
            #pragma unroll
            for (int q = 0; q < CL; q++)
                acc += sm[OFF_RSLOT + q * kS + t];
            sm[OFF_H + t] = acc;
        }
        __syncthreads();
    }

    // final readout (n = NWIN), rank 0 only
    if (rank == 0 && t < kOut) {
        float acc = sm[OFF_BR + t];
        #pragma unroll
        for (int a = 0; a < kS; a++)
            acc = fmaf(sm[OFF_WR + t * kS + a], sm[OFF_H + a], acc);
        out[((size_t)b * (kNW + 1) + kNW) * kOut + t] = acc;
    }
}

extern "C" void kernel_launch(void* const* d_in, const int* in_sizes, int n_in,
                              void* d_out, int out_size) {
    // metadata order: ts, x, Wi0,bi0, Wi1,bi1, Wi2,bi2, Wv0,bv0, Wv1,bv1, Wv2,bv2, Wr,br
    const float* x   = (const float*)d_in[1];
    const float* Wi0 = (const float*)d_in[2];
    const float* bi0 = (const float*)d_in[3];
    const float* Wi1 = (const float*)d_in[4];
    const float* bi1 = (const float*)d_in[5];
    const float* Wi2 = (const float*)d_in[6];
    const float* bi2 = (const float*)d_in[7];
    const float* Wv0 = (const float*)d_in[8];
    const float* bv0 = (const float*)d_in[9];
    const float* Wv1 = (const float*)d_in[10];
    const float* bv1 = (const float*)d_in[11];
    const float* Wv2 = (const float*)d_in[12];
    const float* bv2 = (const float*)d_in[13];
    const float* Wr  = (const float*)d_in[14];
    const float* br  = (const float*)d_in[15];
    float* out = (float*)d_out;

    cudaFuncSetAttribute(logncde_cluster_kernel,
                         cudaFuncAttributeMaxDynamicSharedMemorySize,
                         SMEMF * (int)sizeof(float));
    logncde_cluster_kernel<<<kB * CL, NT, SMEMF * sizeof(float)>>>(
        x, Wi0, bi0, Wi1, bi1, Wi2, bi2,
        Wv0, bv0, Wv1, bv1, Wv2, bv2, Wr, br, out);
}

// round 3
// speedup vs baseline: 3.1599x; 1.7231x over previous
#include <cuda_runtime.h>
#include <cooperative_groups.h>
#include <math.h>

namespace cg = cooperative_groups;

// ---------------------------------------------------------------------------
// LogNCDE depth-2 log-ODE scan, 4-CTA cluster per batch element.
// Rank r owns channels d in {2r,2r+1} and Wv2 rows [128r,128r+128).
// All vf weights live in per-thread REGISTERS (4-row x k-chunk tiles);
// activations are broadcast from smem; partials reduced through smem.
// ---------------------------------------------------------------------------

namespace {
constexpr int kB   = 32;
constexpr int kT   = 2049;
constexpr int kD   = 8;
constexpr int kS   = 64;
constexpr int kH   = 128;
constexpr int kP   = 28;
constexpr int kNW  = 128;
constexpr int kWin = 16;
constexpr int kOut = 8;
constexpr int CL   = 4;
constexpr int NT   = 256;

// shared-memory layout (float offsets; all float4-aligned)
constexpr int OFF_SIGS  = 0;                  // [n<128][36]
constexpr int OFF_BV0   = 4608;               // 128
constexpr int OFF_BV1   = 4736;               // 128
constexpr int OFF_BV2S  = 4864;               // 128 (slice)
constexpr int OFF_WR    = 4992;               // [o<8][a<64]
constexpr int OFF_BR    = 5504;               // 8 (+pad)
constexpr int OFF_H     = 5520;               // 64
constexpr int OFF_Z0    = 5584;               // 128
constexpr int OFF_D0    = 5712;               // 128
constexpr int OFF_Z1    = 5840;               // 128
constexpr int OFF_D1    = 5968;               // 128
constexpr int OFF_V     = 6096;               // 2 x 512 double buffer
constexpr int OFF_TDS   = 7120;               // 128 own slice: 1 - V^2
constexpr int OFF_C     = 7248;               // 2 x 8 (+pad)
constexpr int OFF_WT    = 7264;               // 2 x 64 tangents
constexpr int OFF_PT    = 7392;               // 2 x 128
constexpr int OFF_UT    = 7648;               // 2 x 128
constexpr int OFF_RSLOT = 7904;               // 4 x 64
constexpr int OFF_PART  = 8160;               // 2 x 8 x 128 partials
constexpr int SMEMF     = 10208;              // ~40 KB
}  // namespace

static __device__ const int c_II[kP] =
    {0,0,0,0,0,0,0,1,1,1,1,1,1,2,2,2,2,2,3,3,3,3,4,4,4,5,5,6};
static __device__ const int c_JJ[kP] =
    {1,2,3,4,5,6,7,2,3,4,5,6,7,3,4,5,6,7,4,5,6,7,5,6,7,6,7,7};

__device__ __forceinline__ float sp_f(float x) {
    return (x > 20.f) ? x : log1pf(expf(x));
}
__device__ __forceinline__ float sg_f(float x) {
    return 1.f / (1.f + expf(-x));
}
__device__ __forceinline__ int pidx(int i, int j) {   // Lyndon pair index, i<j
    return 7 * i - (i * (i - 1)) / 2 + (j - i - 1);
}
__device__ __forceinline__ float dot4(float4 w, float4 v, float acc) {
    acc = fmaf(w.x, v.x, acc); acc = fmaf(w.y, v.y, acc);
    acc = fmaf(w.z, v.z, acc); acc = fmaf(w.w, v.w, acc);
    return acc;
}

__global__ __launch_bounds__(NT, 1) __cluster_dims__(CL, 1, 1)
void logncde_reg_kernel(
    const float* __restrict__ x,
    const float* __restrict__ Wi0, const float* __restrict__ bi0,
    const float* __restrict__ Wi1, const float* __restrict__ bi1,
    const float* __restrict__ Wi2, const float* __restrict__ bi2,
    const float* __restrict__ Wv0, const float* __restrict__ bv0,
    const float* __restrict__ Wv1, const float* __restrict__ bv1,
    const float* __restrict__ Wv2, const float* __restrict__ bv2,
    const float* __restrict__ Wr,  const float* __restrict__ br,
    float* __restrict__ out)
{
    extern __shared__ float sm[];
    cg::cluster_group cluster = cg::this_cluster();
    const int t    = threadIdx.x;
    const int rank = (int)cluster.block_rank();
    const int b    = blockIdx.x >> 2;
    const int d0g  = 2 * rank;
    const int og   = t & 31;     // output group: rows 4og..4og+3
    const int kg   = t >> 5;     // k-chunk id == warp id (broadcast-friendly)

    float* peer[CL - 1];
    #pragma unroll
    for (int p = 1; p < CL; p++)
        peer[p - 1] = cluster.map_shared_rank(sm, (rank + p) & (CL - 1));

    // ---- register weight tiles (loaded once from gmem) ----
    // Wv0 [o<128][k<64]  : 4 rows x 8k  -> 8  float4
    // Wv1 [o<128][k<128] : 4 rows x 16k -> 16 float4
    // Wv2 slice [og<128][k<128] (global rows 128*rank+og) -> 16 float4
    float4 w0r[8], w1r[16], w2r[16];
    {
        const float4* W0 = (const float4*)Wv0;
        #pragma unroll
        for (int r = 0; r < 4; r++)
            #pragma unroll
            for (int j = 0; j < 2; j++)
                w0r[r * 2 + j] = W0[(4 * og + r) * 16 + kg * 2 + j];
        const float4* W1 = (const float4*)Wv1;
        #pragma unroll
        for (int r = 0; r < 4; r++)
            #pragma unroll
            for (int j = 0; j < 4; j++)
                w1r[r * 4 + j] = W1[(4 * og + r) * 32 + kg * 4 + j];
        const float4* W2 = (const float4*)Wv2;
        #pragma unroll
        for (int r = 0; r < 4; r++)
            #pragma unroll
            for (int j = 0; j < 4; j++)
                w2r[r * 4 + j] = W2[(kH * rank + 4 * og + r) * 32 + kg * 4 + j];
    }

    // ---- one-time smem staging: biases, readout, signatures ----
    for (int i = t; i < kH; i += NT) {
        sm[OFF_BV0 + i]  = bv0[i];
        sm[OFF_BV1 + i]  = bv1[i];
        sm[OFF_BV2S + i] = bv2[kH * rank + i];
    }
    for (int i = t; i < kOut * kS; i += NT) sm[OFF_WR + i] = Wr[i];
    if (t < kOut) sm[OFF_BR + t] = br[t];

    if (t < kNW) {
        const float* xb = x + (size_t)b * kT * kD + (size_t)t * kWin * kD;
        float cum[kD], prev[kD], Mm[kD * kD];
        #pragma unroll
        for (int i = 0; i < kD; i++) { cum[i] = 0.f; prev[i] = xb[i]; }
        #pragma unroll
        for (int i = 0; i < kD * kD; i++) Mm[i] = 0.f;
        for (int w = 0; w < kWin; w++) {
            float dl[kD];
            #pragma unroll
            for (int j = 0; j < kD; j++) {
                float c = xb[(w + 1) * kD + j];
                dl[j] = c - prev[j];
                prev[j] = c;
            }
            #pragma unroll
            for (int i = 0; i < kD; i++)
                #pragma unroll
                for (int j = 0; j < kD; j++)
                    Mm[i * kD + j] = fmaf(cum[i], dl[j], Mm[i * kD + j]);
            #pragma unroll
            for (int i = 0; i < kD; i++) cum[i] += dl[i];
        }
        float* sgw = &sm[OFF_SIGS + t * 36];
        #pragma unroll
        for (int i = 0; i < kD; i++) sgw[i] = cum[i];
        #pragma unroll
        for (int p = 0; p < kP; p++) {
            int i = c_II[p], j = c_JJ[p];
            sgw[8 + p] = 0.5f * (Mm[i * kD + j] - Mm[j * kD + i]);
        }
    }
    __syncthreads();

    // ---- one-time: initial MLP h0 (replicated across ranks) ----
    {
        const float* x0 = x + (size_t)b * kT * kD;
        if (t < kH) {
            float acc = bi0[t];
            #pragma unroll
            for (int k = 0; k < kD; k++) acc = fmaf(Wi0[t * kD + k], x0[k], acc);
            sm[OFF_Z0 + t] = sp_f(acc);
        }
        __syncthreads();
        if (t < kH) {
            float acc = bi1[t];
            #pragma unroll 16
            for (int k = 0; k < kH; k++) acc = fmaf(Wi1[t * kH + k], sm[OFF_Z0 + k], acc);
            sm[OFF_Z1 + t] = sp_f(acc);
        }
        __syncthreads();
        if (t < kS) {
            float acc = bi2[t];
            #pragma unroll 16
            for (int k = 0; k < kH; k++) acc = fmaf(Wi2[t * kH + k], sm[OFF_Z1 + k], acc);
            sm[OFF_H + t] = acc;
        }
        __syncthreads();
    }

    cluster.sync();

    float4* part4 = (float4*)&sm[OFF_PART];

    // ============================ scan loop ============================
    for (int n = 0; n < kNW; n++) {
        const float* sgn = &sm[OFF_SIGS + n * 36];
        const int parV = (n & 1) * 512;

        // --- A: partials of z0 = Wv0 h  (weights in regs, h broadcast)
        {
            const float4* h4 = (const float4*)&sm[OFF_H];
            float4 a = make_float4(0.f, 0.f, 0.f, 0.f);
            #pragma unroll
            for (int j = 0; j < 2; j++) {
                float4 hv = h4[kg * 2 + j];
                a.x = dot4(w0r[0 * 2 + j], hv, a.x);
                a.y = dot4(w0r[1 * 2 + j], hv, a.y);
                a.z = dot4(w0r[2 * 2 + j], hv, a.z);
                a.w = dot4(w0r[3 * 2 + j], hv, a.w);
            }
            part4[kg * 32 + og] = a;
        }
        __syncthreads();
        // A-reduce (z0,d0); rank0 readout of h_n; C coeff build
        if (t < kH) {
            float s = sm[OFF_BV0 + t];
            #pragma unroll
            for (int q = 0; q < 8; q++) s += sm[OFF_PART + q * kH + t];
            sm[OFF_Z0 + t] = sp_f(s);
            sm[OFF_D0 + t] = sg_f(s);
        } else if (t < kH + kOut) {
            if (rank == 0) {
                int o = t - kH;
                float acc = sm[OFF_BR + o];
                #pragma unroll
                for (int a = 0; a < kS; a++)
                    acc = fmaf(sm[OFF_WR + o * kS + a], sm[OFF_H + a], acc);
                out[((size_t)b * (kNW + 1) + n) * kOut + o] = acc;
            }
        } else if (t >= kH + 16 && t < kH + 32) {
            int idx = t - kH - 16;
            int dl = idx >> 3, e = idx & 7;
            int d = d0g + dl;
            float v = 0.f;
            if (e < d)      v =  sgn[8 + pidx(e, d)];
            else if (e > d) v = -sgn[8 + pidx(d, e)];
            sm[OFF_C + dl * 8 + e] = v;
        }
        __syncthreads();

        // --- B: partials of z1 = Wv1 z0
        {
            const float4* z4 = (const float4*)&sm[OFF_Z0];
            float4 a = make_float4(0.f, 0.f, 0.f, 0.f);
            #pragma unroll
            for (int j = 0; j < 4; j++) {
                float4 zv = z4[kg * 4 + j];
                a.x = dot4(w1r[0 * 4 + j], zv, a.x);
                a.y = dot4(w1r[1 * 4 + j], zv, a.y);
                a.z = dot4(w1r[2 * 4 + j], zv, a.z);
                a.w = dot4(w1r[3 * 4 + j], zv, a.w);
            }
            part4[kg * 32 + og] = a;
        }
        __syncthreads();
        if (t < kH) {
            float s = sm[OFF_BV1 + t];
            #pragma unroll
            for (int q = 0; q < 8; q++) s += sm[OFF_PART + q * kH + t];
            sm[OFF_Z1 + t] = sp_f(s);
            sm[OFF_D1 + t] = sg_f(s);
        }
        __syncthreads();

        // --- C: partials of V slice = Wv2_slice z1
        {
            const float4* z4 = (const float4*)&sm[OFF_Z1];
            float4 a = make_float4(0.f, 0.f, 0.f, 0.f);
            #pragma unroll
            for (int j = 0; j < 4; j++) {
                float4 zv = z4[kg * 4 + j];
                a.x = dot4(w2r[0 * 4 + j], zv, a.x);
                a.y = dot4(w2r[1 * 4 + j], zv, a.y);
                a.z = dot4(w2r[2 * 4 + j], zv, a.z);
                a.w = dot4(w2r[3 * 4 + j], zv, a.w);
            }
            part4[kg * 32 + og] = a;
        }
        __syncthreads();
        if (t < kH) {
            float s = sm[OFF_BV2S + t];
            #pragma unroll
            for (int q = 0; q < 8; q++) s += sm[OFF_PART + q * kH + t];
            float v = tanhf(s);
            int vi = OFF_V + parV + kH * rank + t;
            sm[vi] = v;
            sm[OFF_TDS + t] = 1.f - v * v;
            peer[0][vi] = v;
            peer[1][vi] = v;
            peer[2][vi] = v;
        }
        cluster.sync();   // V(n) gathered everywhere

        // --- D: tangents w_d = sum_e C[d,e] V_e (own 2 channels)
        if (t < kH) {
            int dl = t >> 6, a_ = t & 63;
            float acc = 0.f;
            #pragma unroll
            for (int e = 0; e < kD; e++)
                acc = fmaf(sm[OFF_C + dl * 8 + e], sm[OFF_V + parV + e * kS + a_], acc);
            sm[OFF_WT + dl * kS + a_] = acc;
        }
        __syncthreads();

        // --- E: partials of q_d = Wv0 w_d (2 channels, shared weight regs)
        {
            const float4* wt4 = (const float4*)&sm[OFF_WT];
            float4 a0 = make_float4(0.f, 0.f, 0.f, 0.f);
            float4 a1 = make_float4(0.f, 0.f, 0.f, 0.f);
            #pragma unroll
            for (int j = 0; j < 2; j++) {
                float4 v0 = wt4[kg * 2 + j];
                float4 v1 = wt4[16 + kg * 2 + j];
                a0.x = dot4(w0r[0 * 2 + j], v0, a0.x);
                a0.y = dot4(w0r[1 * 2 + j], v0, a0.y);
                a0.z = dot4(w0r[2 * 2 + j], v0, a0.z);
                a0.w = dot4(w0r[3 * 2 + j], v0, a0.w);
                a1.x = dot4(w0r[0 * 2 + j], v1, a1.x);
                a1.y = dot4(w0r[1 * 2 + j], v1, a1.y);
                a1.z = dot4(w0r[2 * 2 + j], v1, a1.z);
                a1.w = dot4(w0r[3 * 2 + j], v1, a1.w);
            }
            part4[kg * 32 + og] = a0;
            part4[256 + kg * 32 + og] = a1;
        }
        __syncthreads();
        {   // pt = D0 .* q
            int dl = t >> 7, o = t & 127;
            float s = 0.f;
            #pragma unroll
            for (int q = 0; q < 8; q++)
                s += sm[OFF_PART + dl * 1024 + q * kH + o];
            sm[OFF_PT + dl * kH + o] = s * sm[OFF_D0 + o];
        }
        __syncthreads();

        // --- F: partials of u'_d = Wv1 p_d (2 channels)
        {
            const float4* pt4 = (const float4*)&sm[OFF_PT];
            float4 a0 = make_float4(0.f, 0.f, 0.f, 0.f);
            float4 a1 = make_float4(0.f, 0.f, 0.f, 0.f);
            #pragma unroll
            for (int j = 0; j < 4; j++) {
                float4 v0 = pt4[kg * 4 + j];
                float4 v1 = pt4[32 + kg * 4 + j];
                a0.x = dot4(w1r[0 * 4 + j], v0, a0.x);
                a0.y = dot4(w1r[1 * 4 + j], v0, a0.y);
                a0.z = dot4(w1r[2 * 4 + j], v0, a0.z);
                a0.w = dot4(w1r[3 * 4 + j], v0, a0.w);
                a1.x = dot4(w1r[0 * 4 + j], v1, a1.x);
                a1.y = dot4(w1r[1 * 4 + j], v1, a1.y);
                a1.z = dot4(w1r[2 * 4 + j], v1, a1.z);
                a1.w = dot4(w1r[3 * 4 + j], v1, a1.w);
            }
            part4[kg * 32 + og] = a0;
            part4[256 + kg * 32 + og] = a1;
        }
        __syncthreads();
        {   // ut = D1 .* u'
            int dl = t >> 7, o = t & 127;
            float s = 0.f;
            #pragma unroll
            for (int q = 0; q < 8; q++)
                s += sm[OFF_PART + dl * 1024 + q * kH + o];
            sm[OFF_UT + dl * kH + o] = s * sm[OFF_D1 + o];
        }
        __syncthreads();

        // --- G: partials of r = Wv2_slice u_{dl(row)}  (row-dependent RHS)
        {
            int dl = og >> 4;   // rows 4og..4og+3 all in channel dl
            const float4* u4 = (const float4*)&sm[OFF_UT + dl * kH];
            float4 a = make_float4(0.f, 0.f, 0.f, 0.f);
            #pragma unroll
            for (int j = 0; j < 4; j++) {
                float4 uv = u4[kg * 4 + j];
                a.x = dot4(w2r[0 * 4 + j], uv, a.x);
                a.y = dot4(w2r[1 * 4 + j], uv, a.y);
                a.z = dot4(w2r[2 * 4 + j], uv, a.z);
                a.w = dot4(w2r[3 * 4 + j], uv, a.w);
            }
            part4[kg * 32 + og] = a;
        }
        __syncthreads();
        // G-reduce: apply TD, fold the 2 channels, push to peers
        if (t < kS) {
            float s0 = 0.f, s1 = 0.f;
            #pragma unroll
            for (int q = 0; q < 8; q++) {
                s0 += sm[OFF_PART + q * kH + t];
                s1 += sm[OFF_PART + q * kH + kS + t];
            }
            float rs = s0 * sm[OFF_TDS + t] + s1 * sm[OFF_TDS + kS + t];
            int ri = OFF_RSLOT + kS * rank + t;
            sm[ri] = rs;
            peer[0][ri] = rs;
            peer[1][ri] = rs;
            peer[2][ri] = rs;
        }
        cluster.sync();   // bracket partials gathered everywhere

        // --- H: h += a.V + sum_r rslot (replicated)
        if (t < kS) {
            float acc = sm[OFF_H + t];
            #pragma unroll
            for (int d = 0; d < kD; d++)
                acc = fmaf(sgn[d], sm[OFF_V + parV + d * kS + t], acc);
            #pragma unroll
            for (int q = 0; q < CL; q++)
                acc += sm[OFF_RSLOT + q * kS + t];
            sm[OFF_H + t] = acc;
        }
        __syncthreads();
    }

    // final readout (n = NWIN), rank 0 only
    if (rank == 0 && t < kOut) {
        float acc = sm[OFF_BR + t];
        #pragma unroll
        for (int a = 0; a < kS; a++)
            acc = fmaf(sm[OFF_WR + t * kS + a], sm[OFF_H + a], acc);
        out[((size_t)b * (kNW + 1) + kNW) * kOut + t] = acc;
    }
}

extern "C" void kernel_launch(void* const* d_in, const int* in_sizes, int n_in,
                              void* d_out, int out_size) {
    // metadata order: ts, x, Wi0,bi0, Wi1,bi1, Wi2,bi2, Wv0,bv0, Wv1,bv1, Wv2,bv2, Wr,br
    const float* x   = (const float*)d_in[1];
    const float* Wi0 = (const float*)d_in[2];
    const float* bi0 = (const float*)d_in[3];
    const float* Wi1 = (const float*)d_in[4];
    const float* bi1 = (const float*)d_in[5];
    const float* Wi2 = (const float*)d_in[6];
    const float* bi2 = (const float*)d_in[7];
    const float* Wv0 = (const float*)d_in[8];
    const float* bv0 = (const float*)d_in[9];
    const float* Wv1 = (const float*)d_in[10];
    const float* bv1 = (const float*)d_in[11];
    const float* Wv2 = (const float*)d_in[12];
    const float* bv2 = (const float*)d_in[13];
    const float* Wr  = (const float*)d_in[14];
    const float* br  = (const float*)d_in[15];
    float* out = (float*)d_out;

    cudaFuncSetAttribute(logncde_reg_kernel,
                         cudaFuncAttributeMaxDynamicSharedMemorySize,
                         SMEMF * (int)sizeof(float));
    logncde_reg_kernel<<<kB * CL, NT, SMEMF * sizeof(float)>>>(
        x, Wi0, bi0, Wi1, bi1, Wi2, bi2,
        Wv0, bv0, Wv1, bv1, Wv2, bv2, Wr, br, out);
}